// round 5
// baseline (speedup 1.0000x reference)
#include <cuda_runtime.h>
#include <cuda_bf16.h>
#include <cstdint>

// Problem constants
constexpr int cB = 8;
constexpr int cN = 1024;
constexpr int cC = 640;
constexpr int cH = 8;
constexpr int cD = 80;
constexpr int cR = 3;
constexpr int cInner = cH * cD;        // 640
constexpr int cM = cB * cN;            // 8192
constexpr float SCALE = 0.11180339887498949f;  // 80^-0.5

// Scratch
__device__ float g_q[cM * cInner];
__device__ float g_k[cM * cInner];
__device__ float g_v[cM * cInner];
__device__ float g_ao[cM * cInner];

// ---------------------------------------------------------------------------
// helpers
// ---------------------------------------------------------------------------
__device__ __forceinline__ uint32_t smem_u32(const void* p) {
    uint32_t a;
    asm("{ .reg .u64 t; cvta.to.shared.u64 t, %1; cvt.u32.u64 %0, t; }"
        : "=r"(a) : "l"(p));
    return a;
}
__device__ __forceinline__ uint32_t tf32r(float x) {
    uint32_t r;
    asm("cvt.rna.tf32.f32 %0, %1;" : "=r"(r) : "f"(x));
    return r;
}
__device__ __forceinline__ float tf32rf(float x) {
    return __uint_as_float(tf32r(x));
}
__device__ __forceinline__ void mma_tf32(float* c, const uint32_t* a,
                                         uint32_t b0, uint32_t b1) {
    asm volatile(
        "mma.sync.aligned.m16n8k8.row.col.f32.tf32.tf32.f32 "
        "{%0,%1,%2,%3}, {%4,%5,%6,%7}, {%8,%9}, {%0,%1,%2,%3};"
        : "+f"(c[0]), "+f"(c[1]), "+f"(c[2]), "+f"(c[3])
        : "r"(a[0]), "r"(a[1]), "r"(a[2]), "r"(a[3]), "r"(b0), "r"(b1));
}
__device__ __forceinline__ void cp_async16(uint32_t dst, const void* src) {
    asm volatile("cp.async.ca.shared.global [%0], [%1], 16;" :: "r"(dst), "l"(src));
}
__device__ __forceinline__ void cp_commit() {
    asm volatile("cp.async.commit_group;" ::: "memory");
}
template <int N>
__device__ __forceinline__ void cp_wait() {
    asm volatile("cp.async.wait_group %0;" :: "n"(N) : "memory");
}

// ---------------------------------------------------------------------------
// tf32 tensor-core GEMM with cp.async double-buffered pipeline.
// C[M,Nc] = A[M,K] * B[Nc,K]^T (+bias). 128x128 tile, BK=32, 8 warps (2x4).
// Smem holds RAW fp32 (pitch 36 words -> conflict-free scalar frag loads);
// tf32 rounding happens at fragment load (same rounding points as before).
// ---------------------------------------------------------------------------
constexpr int GP2  = 36;                    // smem row pitch (words)
constexpr int GBUF = 128 * GP2;             // words per buffer per operand
constexpr int GEMM_SMEM = 4 * GBUF * 4;     // 2 operands x 2 buffers = 73728 B

__global__ __launch_bounds__(256, 2) void gemm_tf32(
    const float* __restrict__ A, const float* __restrict__ Bm,
    float* __restrict__ C, const float* __restrict__ bias,
    int M, int Nc, int K)
{
    extern __shared__ float gsm[];
    float* As = gsm;                 // [2][GBUF]
    float* Bs = gsm + 2 * GBUF;      // [2][GBUF]

    const int tid  = threadIdx.x;
    const int wid  = tid >> 5;
    const int lane = tid & 31;
    const int gid  = lane >> 2;
    const int tig  = lane & 3;
    const int wm   = (wid & 1) * 64;
    const int wn   = (wid >> 1) * 32;

    const int srow = tid >> 1;           // 0..127
    const int skc  = (tid & 1) * 16;     // k offset 0/16

    const float* Ap = A  + (size_t)(blockIdx.y * 128 + srow) * K + skc;
    const float* Bp = Bm + (size_t)(blockIdx.x * 128 + srow) * K + skc;
    const uint32_t sA = smem_u32(As) + (srow * GP2 + skc) * 4;
    const uint32_t sB = smem_u32(Bs) + (srow * GP2 + skc) * 4;
    const uint32_t bufB = GBUF * 4;      // bytes per buffer

    float acc[4][4][4];
#pragma unroll
    for (int mi = 0; mi < 4; mi++)
#pragma unroll
        for (int nj = 0; nj < 4; nj++)
#pragma unroll
            for (int j = 0; j < 4; j++) acc[mi][nj][j] = 0.f;

    const int nk = K >> 5;

    // prologue: stage k-block 0 into buffer 0
#pragma unroll
    for (int i = 0; i < 4; i++) {
        cp_async16(sA + i * 16, Ap + i * 4);
        cp_async16(sB + i * 16, Bp + i * 4);
    }
    cp_commit();

#pragma unroll 1
    for (int t = 0; t < nk; t++) {
        if (t + 1 < nk) {
            const uint32_t bo = (uint32_t)((t + 1) & 1) * bufB;
            const float* ap = Ap + (t + 1) * 32;
            const float* bp = Bp + (t + 1) * 32;
#pragma unroll
            for (int i = 0; i < 4; i++) {
                cp_async16(sA + bo + i * 16, ap + i * 4);
                cp_async16(sB + bo + i * 16, bp + i * 4);
            }
            cp_commit();
            cp_wait<1>();
        } else {
            cp_wait<0>();
        }
        __syncthreads();

        const float* Ab = As + (t & 1) * GBUF;
        const float* Bb = Bs + (t & 1) * GBUF;

#pragma unroll
        for (int ks = 0; ks < 4; ks++) {
            uint32_t af[4][4];
#pragma unroll
            for (int mi = 0; mi < 4; mi++) {
                const float* p0 = Ab + (wm + mi * 16 + gid) * GP2 + ks * 8 + tig;
                af[mi][0] = tf32r(p0[0]);
                af[mi][1] = tf32r(p0[8 * GP2]);
                af[mi][2] = tf32r(p0[4]);
                af[mi][3] = tf32r(p0[8 * GP2 + 4]);
            }
#pragma unroll
            for (int nj = 0; nj < 4; nj++) {
                const float* p = Bb + (wn + nj * 8 + gid) * GP2 + ks * 8 + tig;
                const uint32_t b0 = tf32r(p[0]);
                const uint32_t b1 = tf32r(p[4]);
#pragma unroll
                for (int mi = 0; mi < 4; mi++)
                    mma_tf32(acc[mi][nj], af[mi], b0, b1);
            }
        }
        __syncthreads();
    }

    // epilogue
#pragma unroll
    for (int nj = 0; nj < 4; nj++) {
        const int col = blockIdx.x * 128 + wn + nj * 8 + tig * 2;
        const float ba0 = bias ? bias[col]     : 0.f;
        const float ba1 = bias ? bias[col + 1] : 0.f;
#pragma unroll
        for (int mi = 0; mi < 4; mi++) {
            const int row = blockIdx.y * 128 + wm + mi * 16 + gid;
            float* cp = C + (size_t)row * Nc + col;
            *(float2*)cp = make_float2(acc[mi][nj][0] + ba0, acc[mi][nj][1] + ba1);
            *(float2*)(cp + (size_t)8 * Nc) =
                make_float2(acc[mi][nj][2] + ba0, acc[mi][nj][3] + ba1);
        }
    }
}

// ---------------------------------------------------------------------------
// Flash attention, mma.sync tf32. Re-tiled for occupancy:
// 128-thread CTA (4 warps), 64-query x 64-key tiles, 3 CTAs/SM.
// Grid (16 qtiles, 8 heads, 8 frames) = 1024 CTAs.
// Fragment layouts identical to the proven round-3 kernel, dimensions halved.
// ---------------------------------------------------------------------------
constexpr int QSP = 84;                   // Qs pitch
constexpr int KTP = 72;                   // Kt pitch (64 keys + 8; %32==8)
constexpr int VSP = 88;                   // Vs pitch (%32==24)
constexpr int SM_QS = 0;                  // word offsets
constexpr int SM_KT = 64 * QSP;           // 5376
constexpr int SM_VS = SM_KT + 80 * KTP;   // 11136
constexpr int ATTN_SMEM = (SM_VS + 64 * VSP) * 4;   // 67072 bytes

__global__ __launch_bounds__(128, 3) void attn_mma(const int* __restrict__ ctx)
{
    extern __shared__ float sm[];
    float* Qs = sm + SM_QS;
    float* Kt = sm + SM_KT;
    float* Vs = sm + SM_VS;

    const int tid  = threadIdx.x;
    const int wid  = tid >> 5;      // 0..3
    const int lane = tid & 31;
    const int gid  = lane >> 2;
    const int tig  = lane & 3;
    const int m0   = wid * 16;      // warp's first query row (0..48)

    const int qt = blockIdx.x, h = blockIdx.y, b = blockIdx.z;

    const int r0 = tid >> 1;           // 0..63
    const int d0 = (tid & 1) * 40;     // 0/40

    // ---- stage Q (64 x 80, SCALE folded, tf32-rounded) ----
    {
        const float* qp = g_q + (size_t)(b * cN + qt * 64 + r0) * cInner + h * cD + d0;
        float* qs = Qs + r0 * QSP + d0;
#pragma unroll
        for (int i = 0; i < 10; i++) {
            float4 v = *(const float4*)(qp + i * 4);
            qs[i * 4 + 0] = tf32rf(v.x * SCALE);
            qs[i * 4 + 1] = tf32rf(v.y * SCALE);
            qs[i * 4 + 2] = tf32rf(v.z * SCALE);
            qs[i * 4 + 3] = tf32rf(v.w * SCALE);
        }
    }
    __syncthreads();

    // ---- Q A-fragments in registers (reused for all 48 KV tiles) ----
    uint32_t qa[10][4];
#pragma unroll
    for (int k = 0; k < 10; k++) {
        qa[k][0] = __float_as_uint(Qs[(m0 + gid) * QSP + k * 8 + tig]);
        qa[k][1] = __float_as_uint(Qs[(m0 + gid + 8) * QSP + k * 8 + tig]);
        qa[k][2] = __float_as_uint(Qs[(m0 + gid) * QSP + k * 8 + tig + 4]);
        qa[k][3] = __float_as_uint(Qs[(m0 + gid + 8) * QSP + k * 8 + tig + 4]);
    }

    float o[10][4];
#pragma unroll
    for (int n = 0; n < 10; n++)
#pragma unroll
        for (int j = 0; j < 4; j++) o[n][j] = 0.f;
    float mlo = -1e30f, mhi = -1e30f, llo = 0.f, lhi = 0.f;

    const int sh1 = (lane & 28) | (tig >> 1);
    const int sh2 = sh1 + 2;
    const bool odd = (tig & 1);

#pragma unroll 1
    for (int t = 0; t < 48; t++) {
        __syncthreads();

        // ---- stage K (transposed d-major) and V (64 keys) ----
        {
            const int frame = ctx[b * cR + (t >> 4)];
            const int kb = (t * 64) & (cN - 1);
            const size_t gof = (size_t)(frame * cN + kb + r0) * cInner + h * cD + d0;
            const float* kp = g_k + gof;
            const float* vp = g_v + gof;
            float* vs = Vs + r0 * VSP + d0;
#pragma unroll
            for (int i = 0; i < 10; i++) {
                float4 kv = *(const float4*)(kp + i * 4);
                Kt[(d0 + i * 4 + 0) * KTP + r0] = tf32rf(kv.x);
                Kt[(d0 + i * 4 + 1) * KTP + r0] = tf32rf(kv.y);
                Kt[(d0 + i * 4 + 2) * KTP + r0] = tf32rf(kv.z);
                Kt[(d0 + i * 4 + 3) * KTP + r0] = tf32rf(kv.w);
                float4 vv = *(const float4*)(vp + i * 4);
                *(float4*)(vs + i * 4) = make_float4(
                    tf32rf(vv.x), tf32rf(vv.y), tf32rf(vv.z), tf32rf(vv.w));
            }
        }
        __syncthreads();

        // ---- S = Q K^T : 8 n-tiles x 10 k-steps ----
        float s[8][4];
#pragma unroll
        for (int n = 0; n < 8; n++)
#pragma unroll
            for (int j = 0; j < 4; j++) s[n][j] = 0.f;

#pragma unroll
        for (int n = 0; n < 8; n++) {
            const float* kcol = Kt + n * 8 + gid;
#pragma unroll
            for (int k = 0; k < 10; k++) {
                uint32_t b0 = __float_as_uint(kcol[(k * 8 + tig) * KTP]);
                uint32_t b1 = __float_as_uint(kcol[(k * 8 + tig + 4) * KTP]);
                mma_tf32(s[n], qa[k], b0, b1);
            }
        }

        // ---- online softmax ----
        float mx0 = -1e30f, mx1 = -1e30f;
#pragma unroll
        for (int n = 0; n < 8; n++) {
            mx0 = fmaxf(mx0, fmaxf(s[n][0], s[n][1]));
            mx1 = fmaxf(mx1, fmaxf(s[n][2], s[n][3]));
        }
        mx0 = fmaxf(mx0, __shfl_xor_sync(0xffffffffu, mx0, 1));
        mx0 = fmaxf(mx0, __shfl_xor_sync(0xffffffffu, mx0, 2));
        mx1 = fmaxf(mx1, __shfl_xor_sync(0xffffffffu, mx1, 1));
        mx1 = fmaxf(mx1, __shfl_xor_sync(0xffffffffu, mx1, 2));

        const float mn0 = fmaxf(mlo, mx0);
        const float mn1 = fmaxf(mhi, mx1);
        const float cf0 = __expf(mlo - mn0);
        const float cf1 = __expf(mhi - mn1);
        mlo = mn0; mhi = mn1;

        float rs0 = 0.f, rs1 = 0.f;
#pragma unroll
        for (int n = 0; n < 8; n++) {
            s[n][0] = __expf(s[n][0] - mn0); rs0 += s[n][0];
            s[n][1] = __expf(s[n][1] - mn0); rs0 += s[n][1];
            s[n][2] = __expf(s[n][2] - mn1); rs1 += s[n][2];
            s[n][3] = __expf(s[n][3] - mn1); rs1 += s[n][3];
        }
        rs0 += __shfl_xor_sync(0xffffffffu, rs0, 1);
        rs0 += __shfl_xor_sync(0xffffffffu, rs0, 2);
        rs1 += __shfl_xor_sync(0xffffffffu, rs1, 1);
        rs1 += __shfl_xor_sync(0xffffffffu, rs1, 2);
        llo = llo * cf0 + rs0;
        lhi = lhi * cf1 + rs1;

#pragma unroll
        for (int n = 0; n < 10; n++) {
            o[n][0] *= cf0; o[n][1] *= cf0;
            o[n][2] *= cf1; o[n][3] *= cf1;
        }

        // ---- O += P V : 8 k-tiles x 10 n-tiles ----
#pragma unroll
        for (int kt = 0; kt < 8; kt++) {
            float v00 = __shfl_sync(0xffffffffu, s[kt][0], sh1);
            float v01 = __shfl_sync(0xffffffffu, s[kt][1], sh1);
            float v02 = __shfl_sync(0xffffffffu, s[kt][0], sh2);
            float v03 = __shfl_sync(0xffffffffu, s[kt][1], sh2);
            float v10 = __shfl_sync(0xffffffffu, s[kt][2], sh1);
            float v11 = __shfl_sync(0xffffffffu, s[kt][3], sh1);
            float v12 = __shfl_sync(0xffffffffu, s[kt][2], sh2);
            float v13 = __shfl_sync(0xffffffffu, s[kt][3], sh2);
            uint32_t pa[4];
            pa[0] = tf32r(odd ? v01 : v00);
            pa[1] = tf32r(odd ? v11 : v10);
            pa[2] = tf32r(odd ? v03 : v02);
            pa[3] = tf32r(odd ? v13 : v12);

            const float* vrow0 = Vs + (kt * 8 + tig) * VSP + gid;
            const float* vrow1 = Vs + (kt * 8 + tig + 4) * VSP + gid;
#pragma unroll
            for (int n = 0; n < 10; n++) {
                uint32_t b0 = __float_as_uint(vrow0[n * 8]);
                uint32_t b1 = __float_as_uint(vrow1[n * 8]);
                mma_tf32(o[n], pa, b0, b1);
            }
        }
    }

    // ---- epilogue ----
    const float inv0 = 1.f / llo;
    const float inv1 = 1.f / lhi;
    float* op0 = g_ao + (size_t)(b * cN + qt * 64 + m0 + gid) * cInner + h * cD;
    float* op1 = op0 + (size_t)8 * cInner;
#pragma unroll
    for (int n = 0; n < 10; n++) {
        *(float2*)(op0 + n * 8 + tig * 2) = make_float2(o[n][0] * inv0, o[n][1] * inv0);
        *(float2*)(op1 + n * 8 + tig * 2) = make_float2(o[n][2] * inv1, o[n][3] * inv1);
    }
}

// ---------------------------------------------------------------------------
extern "C" void kernel_launch(void* const* d_in, const int* in_sizes, int n_in,
                              void* d_out, int out_size)
{
    const float* x   = (const float*)d_in[0];
    const float* Wq  = (const float*)d_in[1];
    const float* Wk  = (const float*)d_in[2];
    const float* Wv  = (const float*)d_in[3];
    const float* Wo  = (const float*)d_in[4];
    const float* bo  = (const float*)d_in[5];
    const int*   ctx = (const int*)d_in[6];
    float* out = (float*)d_out;

    float* gq;  cudaGetSymbolAddress((void**)&gq, g_q);
    float* gk;  cudaGetSymbolAddress((void**)&gk, g_k);
    float* gv;  cudaGetSymbolAddress((void**)&gv, g_v);
    float* gao; cudaGetSymbolAddress((void**)&gao, g_ao);

    static bool attr_set = false;
    if (!attr_set) {
        cudaFuncSetAttribute(attn_mma,
                             cudaFuncAttributeMaxDynamicSharedMemorySize,
                             ATTN_SMEM);
        cudaFuncSetAttribute(gemm_tf32,
                             cudaFuncAttributeMaxDynamicSharedMemorySize,
                             GEMM_SMEM);
        attr_set = true;
    }

    const dim3 gg(cInner / 128, cM / 128);   // (5, 64)
    gemm_tf32<<<gg, 256, GEMM_SMEM>>>(x, Wq, gq, nullptr, cM, cInner, cC);
    gemm_tf32<<<gg, 256, GEMM_SMEM>>>(x, Wk, gk, nullptr, cM, cInner, cC);
    gemm_tf32<<<gg, 256, GEMM_SMEM>>>(x, Wv, gv, nullptr, cM, cInner, cC);

    attn_mma<<<dim3(16, 8, 8), 128, ATTN_SMEM>>>(ctx);

    gemm_tf32<<<dim3(cC / 128, cM / 128), 256, GEMM_SMEM>>>(gao, Wo, out, bo, cM, cC, cInner);
}